// round 2
// baseline (speedup 1.0000x reference)
#include <cuda_runtime.h>
#include <cstdint>

#define N_NODES 100000
#define N_EDGES 3200000
#define IN_DIM 64
#define HID_DIM 128
#define OUT_DIM 2

// Scratch (device globals: allocation-free per harness rules)
__device__ __align__(16) float g_agg[N_NODES * IN_DIM];   // 25.6 MB
__device__ int   g_deg[N_NODES];
__device__ float g_dinv[N_NODES];

// ---------------------------------------------------------------------------
// Vector reduction: red.global.add.v4.f32 (sm_90+). 16B per lane-op, 4x fewer
// issue slots than scalar atomicAdd (REDG ~1.29 cyc/lane is the bottleneck).
// ---------------------------------------------------------------------------
__device__ __forceinline__ void red_add_v4(float* addr, float4 v) {
    size_t ga = __cvta_generic_to_global(addr);
    asm volatile("red.global.add.v4.f32 [%0], {%1, %2, %3, %4};"
                 :: "l"(ga), "f"(v.x), "f"(v.y), "f"(v.z), "f"(v.w)
                 : "memory");
}

// ---------------------------------------------------------------------------
// K1: zero agg, deg = 1 (self-loop)
// ---------------------------------------------------------------------------
__global__ void k_init() {
    int i = blockIdx.x * blockDim.x + threadIdx.x;
    const int tot4 = N_NODES * IN_DIM / 4;  // float4 count
    if (i < tot4) {
        reinterpret_cast<float4*>(g_agg)[i] = make_float4(0.f, 0.f, 0.f, 0.f);
    }
    if (i < N_NODES) {
        g_deg[i] = 1;
    }
}

// ---------------------------------------------------------------------------
// K2: in-degree via int atomics over dst  (edge_index is int32: JAX default
// x64-disabled downcasts the reference's int64 request)
// ---------------------------------------------------------------------------
__global__ void k_deg(const int* __restrict__ dst) {
    int e = blockIdx.x * blockDim.x + threadIdx.x;
    if (e < N_EDGES) {
        atomicAdd(&g_deg[__ldg(dst + e)], 1);
    }
}

// ---------------------------------------------------------------------------
// K3: dinv = rsqrt(deg)   (deg >= 1 always, self-loop included)
// ---------------------------------------------------------------------------
__global__ void k_dinv() {
    int i = blockIdx.x * blockDim.x + threadIdx.x;
    if (i < N_NODES) {
        g_dinv[i] = rsqrtf((float)g_deg[i]);
    }
}

// ---------------------------------------------------------------------------
// K4: edge aggregation in 64-dim input space.
// 8 threads per edge; each thread handles two float4 (256B row total).
// Gather x[src] row (L2-resident), scale by dinv[s]*dinv[d], vector-reduce
// into agg[dst] row. Consecutive threads touch consecutive 16B chunks ->
// fully coalesced 256B gather + 256B reduction per edge.
// ---------------------------------------------------------------------------
__global__ void __launch_bounds__(256) k_edge(const float* __restrict__ x,
                                              const int* __restrict__ src,
                                              const int* __restrict__ dst) {
    int t = blockIdx.x * blockDim.x + threadIdx.x;
    int e = t >> 3;
    if (e >= N_EDGES) return;
    int lane = t & 7;

    int s = __ldg(src + e);   // broadcast within the 8-thread group
    int d = __ldg(dst + e);
    float w = __ldg(&g_dinv[s]) * __ldg(&g_dinv[d]);

    const float4* xs = reinterpret_cast<const float4*>(x + (size_t)s * IN_DIM);
    float* ad = g_agg + (size_t)d * IN_DIM;

    float4 v0 = __ldg(xs + lane);
    float4 v1 = __ldg(xs + lane + 8);
    v0.x *= w; v0.y *= w; v0.z *= w; v0.w *= w;
    v1.x *= w; v1.y *= w; v1.z *= w; v1.w *= w;

    red_add_v4(ad + lane * 4, v0);
    red_add_v4(ad + (lane + 8) * 4, v1);
}

// ---------------------------------------------------------------------------
// K5: fused epilogue, one node per thread.
//   y   = agg[i] + x[i] * dinv[i]^2          (self-loop folded in)
//   h   = relu(y @ W_gcn + b_gcn)            (64 -> 128, W_gcn in smem)
//   out = h @ W_lin + b_lin                  (128 -> 2, accumulated inline)
// ---------------------------------------------------------------------------
__global__ void __launch_bounds__(256) k_final(const float* __restrict__ x,
                                               const float* __restrict__ Wg,
                                               const float* __restrict__ bg,
                                               const float* __restrict__ Wl,
                                               const float* __restrict__ bl,
                                               float* __restrict__ out) {
    __shared__ __align__(16) float sWg[IN_DIM * HID_DIM];   // 32 KB
    __shared__ __align__(16) float sWl[HID_DIM * OUT_DIM];  // 1 KB
    __shared__ __align__(16) float sbg[HID_DIM];
    __shared__ float sbl[OUT_DIM];

    // Cooperative smem fill (float4-vectorized)
    const float4* Wg4 = reinterpret_cast<const float4*>(Wg);
    float4* sWg4 = reinterpret_cast<float4*>(sWg);
    for (int i = threadIdx.x; i < IN_DIM * HID_DIM / 4; i += blockDim.x)
        sWg4[i] = Wg4[i];
    for (int i = threadIdx.x; i < HID_DIM * OUT_DIM; i += blockDim.x)
        sWl[i] = Wl[i];
    for (int i = threadIdx.x; i < HID_DIM; i += blockDim.x)
        sbg[i] = bg[i];
    if (threadIdx.x < OUT_DIM) sbl[threadIdx.x] = bl[threadIdx.x];
    __syncthreads();

    const float4* sWgv = reinterpret_cast<const float4*>(sWg);
    const float4* sbgv = reinterpret_cast<const float4*>(sbg);

    for (int i = blockIdx.x * blockDim.x + threadIdx.x; i < N_NODES;
         i += gridDim.x * blockDim.x) {
        float di = g_dinv[i];
        float di2 = di * di;

        float y[IN_DIM];
        const float4* xr = reinterpret_cast<const float4*>(x + (size_t)i * IN_DIM);
        const float4* ar = reinterpret_cast<const float4*>(g_agg + (size_t)i * IN_DIM);
#pragma unroll
        for (int k4 = 0; k4 < IN_DIM / 4; k4++) {
            float4 a = ar[k4];
            float4 b = xr[k4];
            y[4 * k4 + 0] = a.x + b.x * di2;
            y[4 * k4 + 1] = a.y + b.y * di2;
            y[4 * k4 + 2] = a.z + b.z * di2;
            y[4 * k4 + 3] = a.w + b.w * di2;
        }

        float o0 = sbl[0];
        float o1 = sbl[1];

        for (int j4 = 0; j4 < HID_DIM / 4; j4++) {
            float4 acc = sbgv[j4];
#pragma unroll
            for (int k = 0; k < IN_DIM; k++) {
                float4 w = sWgv[k * (HID_DIM / 4) + j4];
                acc.x = fmaf(y[k], w.x, acc.x);
                acc.y = fmaf(y[k], w.y, acc.y);
                acc.z = fmaf(y[k], w.z, acc.z);
                acc.w = fmaf(y[k], w.w, acc.w);
            }
            int j = 4 * j4;
            float h0 = fmaxf(acc.x, 0.f);
            float h1 = fmaxf(acc.y, 0.f);
            float h2 = fmaxf(acc.z, 0.f);
            float h3 = fmaxf(acc.w, 0.f);
            o0 = fmaf(h0, sWl[2 * (j + 0) + 0], o0);
            o1 = fmaf(h0, sWl[2 * (j + 0) + 1], o1);
            o0 = fmaf(h1, sWl[2 * (j + 1) + 0], o0);
            o1 = fmaf(h1, sWl[2 * (j + 1) + 1], o1);
            o0 = fmaf(h2, sWl[2 * (j + 2) + 0], o0);
            o1 = fmaf(h2, sWl[2 * (j + 2) + 1], o1);
            o0 = fmaf(h3, sWl[2 * (j + 3) + 0], o0);
            o1 = fmaf(h3, sWl[2 * (j + 3) + 1], o1);
        }

        out[2 * i + 0] = o0;
        out[2 * i + 1] = o1;
    }
}

// ---------------------------------------------------------------------------
// Launch
// ---------------------------------------------------------------------------
extern "C" void kernel_launch(void* const* d_in, const int* in_sizes, int n_in,
                              void* d_out, int out_size) {
    const float* x     = (const float*)d_in[0];
    const int* ei      = (const int*)d_in[1];   // [2, E] int32: row0=src, row1=dst
    const float* W_gcn = (const float*)d_in[2];
    const float* b_gcn = (const float*)d_in[3];
    const float* W_lin = (const float*)d_in[4];
    const float* b_lin = (const float*)d_in[5];
    float* out         = (float*)d_out;

    const int* src = ei;
    const int* dst = ei + N_EDGES;

    const int T = 256;
    int init_work = N_NODES * IN_DIM / 4;  // float4 zero count (> N_NODES)
    k_init<<<(init_work + T - 1) / T, T>>>();
    k_deg<<<(N_EDGES + T - 1) / T, T>>>(dst);
    k_dinv<<<(N_NODES + T - 1) / T, T>>>();
    k_edge<<<(N_EDGES * 8 + T - 1) / T, T>>>(x, src, dst);
    k_final<<<(N_NODES + T - 1) / T, T>>>(x, W_gcn, b_gcn, W_lin, b_lin, out);
}